// round 1
// baseline (speedup 1.0000x reference)
#include <cuda_runtime.h>
#include <math.h>

#define N_TOT 8192
#define D     128
#define ROWS  64
#define COLS  64
#define PAD   132   // smem row pitch in floats (bank-conflict avoidance)

// Scratch (no cudaMalloc allowed): normalized features + per-row losses
__device__ float g_f[N_TOT * D];
__device__ float g_loss[N_TOT];

__device__ __forceinline__ float fast_exp2(float x) {
    float y;
    asm("ex2.approx.ftz.f32 %0, %1;" : "=f"(y) : "f"(x));
    return y;
}

// ---------------------------------------------------------------------------
// Kernel 1: L2-normalize each row (one warp per row)
// ---------------------------------------------------------------------------
__global__ void normalize_kernel(const float* __restrict__ in) {
    int warp = (blockIdx.x * blockDim.x + threadIdx.x) >> 5;
    int lane = threadIdx.x & 31;
    if (warp >= N_TOT) return;
    float4 v = reinterpret_cast<const float4*>(in + warp * D)[lane];
    float ss = v.x * v.x + v.y * v.y + v.z * v.z + v.w * v.w;
    #pragma unroll
    for (int o = 16; o > 0; o >>= 1)
        ss += __shfl_xor_sync(0xffffffffu, ss, o);
    float nrm = sqrtf(ss);
    float scale = 1.0f / fmaxf(nrm, 1e-12f);
    float4 o4 = make_float4(v.x * scale, v.y * scale, v.z * scale, v.w * scale);
    reinterpret_cast<float4*>(g_f + warp * D)[lane] = o4;
}

// ---------------------------------------------------------------------------
// Kernel 2: fused sim-GEMM + logsumexp + positive-logit extraction
// Block = 256 threads (16x16), owns 64 rows; loops over all 8192 cols in
// 64-wide tiles. Each thread owns a 4x4 micro-tile (rows ty*4+r, cols tx*4+c).
// ---------------------------------------------------------------------------
__global__ void __launch_bounds__(256) simloss_kernel() {
    extern __shared__ float sm[];
    float* As   = sm;                    // ROWS * PAD
    float* Bs   = sm + ROWS * PAD;       // COLS * PAD
    float* part = sm + 2 * ROWS * PAD;   // ROWS: positive logit per local row

    const int t  = threadIdx.x;
    const int tx = t & 15;
    const int ty = t >> 4;
    const int rowBase = blockIdx.x * ROWS;

    // Load A tile (this block's 64 rows)
    for (int i = t; i < ROWS * (D / 4); i += 256) {
        int r = i >> 5;           // i / 32
        int kk = i & 31;          // i % 32 (float4 index)
        float4 v = reinterpret_cast<const float4*>(g_f + (rowBase + r) * D)[kk];
        float* dst = As + r * PAD + kk * 4;
        dst[0] = v.x; dst[1] = v.y; dst[2] = v.z; dst[3] = v.w;
    }
    if (t < ROWS) part[t] = 0.0f;

    float rowsum[4] = {0.f, 0.f, 0.f, 0.f};
    const float invT = 14.285714285714286f;           // 1/0.07
    const float CEXP = 20.609929869842332f;           // log2(e)/0.07

    for (int jt = 0; jt < N_TOT / COLS; jt++) {
        __syncthreads();   // previous tile's compute done before overwriting Bs
        const int colBase = jt * COLS;
        for (int i = t; i < COLS * (D / 4); i += 256) {
            int r = i >> 5;
            int kk = i & 31;
            float4 v = reinterpret_cast<const float4*>(g_f + (colBase + r) * D)[kk];
            float* dst = Bs + r * PAD + kk * 4;
            dst[0] = v.x; dst[1] = v.y; dst[2] = v.z; dst[3] = v.w;
        }
        __syncthreads();

        float s[4][4] = {};
        const float* Ap = As + (ty * 4) * PAD;
        const float* Bp = Bs + (tx * 4) * PAD;

        #pragma unroll 4
        for (int k = 0; k < D; k += 4) {
            float4 a0 = *reinterpret_cast<const float4*>(Ap + 0 * PAD + k);
            float4 a1 = *reinterpret_cast<const float4*>(Ap + 1 * PAD + k);
            float4 a2 = *reinterpret_cast<const float4*>(Ap + 2 * PAD + k);
            float4 a3 = *reinterpret_cast<const float4*>(Ap + 3 * PAD + k);
            float4 b0 = *reinterpret_cast<const float4*>(Bp + 0 * PAD + k);
            float4 b1 = *reinterpret_cast<const float4*>(Bp + 1 * PAD + k);
            float4 b2 = *reinterpret_cast<const float4*>(Bp + 2 * PAD + k);
            float4 b3 = *reinterpret_cast<const float4*>(Bp + 3 * PAD + k);
            float4 aa[4] = {a0, a1, a2, a3};
            float4 bb[4] = {b0, b1, b2, b3};
            #pragma unroll
            for (int r = 0; r < 4; r++) {
                #pragma unroll
                for (int cc = 0; cc < 4; cc++) {
                    s[r][cc] += aa[r].x * bb[cc].x;
                    s[r][cc] += aa[r].y * bb[cc].y;
                    s[r][cc] += aa[r].z * bb[cc].z;
                    s[r][cc] += aa[r].w * bb[cc].w;
                }
            }
        }

        // Epilogue: accumulate exp(s/T) excluding diagonal; capture positive logit
        #pragma unroll
        for (int r = 0; r < 4; r++) {
            const int gi = rowBase + ty * 4 + r;
            #pragma unroll
            for (int cc = 0; cc < 4; cc++) {
                const int gj = colBase + tx * 4 + cc;
                const float sv = s[r][cc];
                if (gi != gj) rowsum[r] += fast_exp2(sv * CEXP);
                if (gj == (gi ^ 4096)) part[ty * 4 + r] = sv * invT;
            }
        }
    }
    __syncthreads();   // make all `part` writes visible

    // Reduce rowsum across the 16 threads (tx) sharing each row
    #pragma unroll
    for (int r = 0; r < 4; r++) {
        float v = rowsum[r];
        #pragma unroll
        for (int o = 8; o > 0; o >>= 1)
            v += __shfl_down_sync(0xffffffffu, v, o, 16);
        rowsum[r] = v;
    }
    if (tx == 0) {
        #pragma unroll
        for (int r = 0; r < 4; r++) {
            const int lr = ty * 4 + r;
            g_loss[rowBase + lr] = logf(rowsum[r]) - part[lr];
        }
    }
}

// ---------------------------------------------------------------------------
// Kernel 3: mean over rows -> output
// ---------------------------------------------------------------------------
__global__ void reduce_kernel(float* __restrict__ out, int out_size) {
    __shared__ float ssum[256];
    float s = 0.0f;
    for (int i = threadIdx.x; i < N_TOT; i += 256) s += g_loss[i];
    ssum[threadIdx.x] = s;
    __syncthreads();
    #pragma unroll
    for (int o = 128; o > 0; o >>= 1) {
        if (threadIdx.x < o) ssum[threadIdx.x] += ssum[threadIdx.x + o];
        __syncthreads();
    }
    const float mean = ssum[0] * (1.0f / (float)N_TOT);
    for (int i = threadIdx.x; i < out_size; i += 256) out[i] = mean;
}

extern "C" void kernel_launch(void* const* d_in, const int* in_sizes, int n_in,
                              void* d_out, int out_size) {
    (void)in_sizes; (void)n_in;
    const float* features = (const float*)d_in[0];
    float* out = (float*)d_out;

    const int smem_bytes = (2 * ROWS * PAD + ROWS) * (int)sizeof(float);
    cudaFuncSetAttribute(simloss_kernel,
                         cudaFuncAttributeMaxDynamicSharedMemorySize, smem_bytes);

    normalize_kernel<<<N_TOT / 8, 256>>>(features);
    simloss_kernel<<<N_TOT / ROWS, 256, smem_bytes>>>();
    reduce_kernel<<<1, 256>>>(out, out_size);
}

// round 2
// speedup vs baseline: 6.5392x; 6.5392x over previous
#include <cuda_runtime.h>
#include <math.h>
#include <stdint.h>

#define N_TOT 8192
#define D     128
#define BM    64     // rows per block
#define BN    128    // cols per tile
#define PA    132    // smem pitch (floats): conflict-free for frag loads
#define PB    132

__device__ float g_f[N_TOT * D];     // tf32-rounded normalized features
__device__ float g_loss[N_TOT];

__device__ __forceinline__ float fast_exp2(float x) {
    float y;
    asm("ex2.approx.ftz.f32 %0, %1;" : "=f"(y) : "f"(x));
    return y;
}

__device__ __forceinline__ float tf32_rna(float x) {
    uint32_t u;
    asm("cvt.rna.tf32.f32 %0, %1;" : "=r"(u) : "f"(x));
    return __uint_as_float(u);
}

__device__ __forceinline__ void mma_tf32(float c[4],
                                         float a0, float a1, float a2, float a3,
                                         float b0, float b1) {
    uint32_t A0 = __float_as_uint(a0), A1 = __float_as_uint(a1);
    uint32_t A2 = __float_as_uint(a2), A3 = __float_as_uint(a3);
    uint32_t B0 = __float_as_uint(b0), B1 = __float_as_uint(b1);
    asm("mma.sync.aligned.m16n8k8.row.col.f32.tf32.tf32.f32 "
        "{%0,%1,%2,%3},{%4,%5,%6,%7},{%8,%9},{%0,%1,%2,%3};"
        : "+f"(c[0]), "+f"(c[1]), "+f"(c[2]), "+f"(c[3])
        : "r"(A0), "r"(A1), "r"(A2), "r"(A3), "r"(B0), "r"(B1));
}

// ---------------------------------------------------------------------------
// Kernel 1: L2-normalize each row, round to tf32 (one warp per row)
// ---------------------------------------------------------------------------
__global__ void normalize_kernel(const float* __restrict__ in) {
    int warp = (blockIdx.x * blockDim.x + threadIdx.x) >> 5;
    int lane = threadIdx.x & 31;
    if (warp >= N_TOT) return;
    float4 v = reinterpret_cast<const float4*>(in + warp * D)[lane];
    float ss = v.x * v.x + v.y * v.y + v.z * v.z + v.w * v.w;
    #pragma unroll
    for (int o = 16; o > 0; o >>= 1)
        ss += __shfl_xor_sync(0xffffffffu, ss, o);
    float scale = 1.0f / fmaxf(sqrtf(ss), 1e-12f);
    float4 o4 = make_float4(tf32_rna(v.x * scale), tf32_rna(v.y * scale),
                            tf32_rna(v.z * scale), tf32_rna(v.w * scale));
    reinterpret_cast<float4*>(g_f + warp * D)[lane] = o4;
}

// ---------------------------------------------------------------------------
// Kernel 2: tf32 tensor-core sim-GEMM + fused logsumexp + positive extraction
// block = 256 threads (8 warps in 4(m) x 2(n)); block tile 64 x 128,
// A (64 rows) resident in smem, B streamed over 64 col-tiles.
// ---------------------------------------------------------------------------
__global__ void __launch_bounds__(256) simloss_kernel() {
    extern __shared__ float sm[];
    float* As   = sm;                       // BM * PA
    float* Bs   = As + BM * PA;             // BN * PB
    float* part = Bs + BN * PB;             // BM : positive logit per row
    float* rsum = part + BM;                // BM * 2 : per-(row, wn) partials

    const int t    = threadIdx.x;
    const int lane = t & 31;
    const int w    = t >> 5;
    const int wm   = w >> 1;                // 0..3
    const int wn   = w & 1;                 // 0..1
    const int g    = lane >> 2;             // 0..7
    const int tg   = lane & 3;              // 0..3
    const int rowBase = blockIdx.x * BM;

    // Stage A tile (64 x 128)
    for (int i = t; i < BM * (D / 4); i += 256) {
        int r = i >> 5, kq = i & 31;
        float4 v = reinterpret_cast<const float4*>(g_f + (rowBase + r) * D)[kq];
        *reinterpret_cast<float4*>(As + r * PA + kq * 4) = v;
    }
    if (t < BM) part[t] = 0.0f;

    const float invT = 14.285714285714286f;   // 1/0.07
    const float CEXP = 20.609929869842332f;   // log2(e)/0.07

    const int jtDiag = rowBase >> 7;
    const int jtPos  = (rowBase ^ 4096) >> 7;

    const float* Aw = As + (wm * 16) * PA;
    const float* Bw = Bs + (wn * 64) * PB;

    float rs0 = 0.0f, rs1 = 0.0f;   // exp-sums for rows (wm*16+g) and (+8)

    for (int jt = 0; jt < N_TOT / BN; jt++) {
        __syncthreads();
        for (int i = t; i < BN * (D / 4); i += 256) {
            int r = i >> 5, kq = i & 31;
            float4 v = reinterpret_cast<const float4*>(g_f + (jt * BN + r) * D)[kq];
            *reinterpret_cast<float4*>(Bs + r * PB + kq * 4) = v;
        }
        __syncthreads();

        float c[8][4];
        #pragma unroll
        for (int nt = 0; nt < 8; nt++)
            c[nt][0] = c[nt][1] = c[nt][2] = c[nt][3] = 0.0f;

        #pragma unroll
        for (int kk = 0; kk < 16; kk++) {
            const int k0 = kk * 8;
            float a0 = Aw[g * PA + k0 + tg];
            float a1 = Aw[(g + 8) * PA + k0 + tg];
            float a2 = Aw[g * PA + k0 + tg + 4];
            float a3 = Aw[(g + 8) * PA + k0 + tg + 4];
            #pragma unroll
            for (int nt = 0; nt < 8; nt++) {
                float b0 = Bw[(nt * 8 + g) * PB + k0 + tg];
                float b1 = Bw[(nt * 8 + g) * PB + k0 + tg + 4];
                mma_tf32(c[nt], a0, a1, a2, a3, b0, b1);
            }
        }

        if (jt != jtDiag && jt != jtPos) {
            // generic epilogue: pure exp-accumulate
            #pragma unroll
            for (int nt = 0; nt < 8; nt++) {
                rs0 += fast_exp2(c[nt][0] * CEXP);
                rs0 += fast_exp2(c[nt][1] * CEXP);
                rs1 += fast_exp2(c[nt][2] * CEXP);
                rs1 += fast_exp2(c[nt][3] * CEXP);
            }
        } else {
            // special tile: diagonal-skip + positive capture
            const int gi0 = rowBase + wm * 16 + g;
            const int gi1 = gi0 + 8;
            const int tj0 = gi0 ^ 4096;
            const int tj1 = gi1 ^ 4096;
            #pragma unroll
            for (int nt = 0; nt < 8; nt++) {
                const int col0 = jt * BN + wn * 64 + nt * 8 + tg * 2;
                const int col1 = col0 + 1;
                if (col0 != gi0) rs0 += fast_exp2(c[nt][0] * CEXP);
                if (col1 != gi0) rs0 += fast_exp2(c[nt][1] * CEXP);
                if (col0 != gi1) rs1 += fast_exp2(c[nt][2] * CEXP);
                if (col1 != gi1) rs1 += fast_exp2(c[nt][3] * CEXP);
                if (col0 == tj0) part[wm * 16 + g]     = c[nt][0] * invT;
                if (col1 == tj0) part[wm * 16 + g]     = c[nt][1] * invT;
                if (col0 == tj1) part[wm * 16 + g + 8] = c[nt][2] * invT;
                if (col1 == tj1) part[wm * 16 + g + 8] = c[nt][3] * invT;
            }
        }
    }

    // Reduce exp-sums over the 4 lanes (tg) sharing each row
    rs0 += __shfl_xor_sync(0xffffffffu, rs0, 1);
    rs0 += __shfl_xor_sync(0xffffffffu, rs0, 2);
    rs1 += __shfl_xor_sync(0xffffffffu, rs1, 1);
    rs1 += __shfl_xor_sync(0xffffffffu, rs1, 2);
    if (tg == 0) {
        rsum[(wm * 16 + g) * 2 + wn]     = rs0;
        rsum[(wm * 16 + g + 8) * 2 + wn] = rs1;
    }
    __syncthreads();

    if (t < BM) {
        float total = rsum[t * 2] + rsum[t * 2 + 1];
        g_loss[rowBase + t] = logf(total) - part[t];
    }
}

// ---------------------------------------------------------------------------
// Kernel 3: mean over rows -> output
// ---------------------------------------------------------------------------
__global__ void reduce_kernel(float* __restrict__ out, int out_size) {
    __shared__ float ssum[256];
    float s = 0.0f;
    for (int i = threadIdx.x; i < N_TOT; i += 256) s += g_loss[i];
    ssum[threadIdx.x] = s;
    __syncthreads();
    #pragma unroll
    for (int o = 128; o > 0; o >>= 1) {
        if (threadIdx.x < o) ssum[threadIdx.x] += ssum[threadIdx.x + o];
        __syncthreads();
    }
    const float mean = ssum[0] * (1.0f / (float)N_TOT);
    for (int i = threadIdx.x; i < out_size; i += 256) out[i] = mean;
}

extern "C" void kernel_launch(void* const* d_in, const int* in_sizes, int n_in,
                              void* d_out, int out_size) {
    (void)in_sizes; (void)n_in;
    const float* features = (const float*)d_in[0];
    float* out = (float*)d_out;

    const int smem_bytes = (BM * PA + BN * PB + BM + BM * 2) * (int)sizeof(float);
    cudaFuncSetAttribute(simloss_kernel,
                         cudaFuncAttributeMaxDynamicSharedMemorySize, smem_bytes);

    normalize_kernel<<<N_TOT / 8, 256>>>(features);
    simloss_kernel<<<N_TOT / BM, 256, smem_bytes>>>();
    reduce_kernel<<<1, 256>>>(out, out_size);
}

// round 3
// speedup vs baseline: 14.9156x; 2.2810x over previous
#include <cuda_runtime.h>
#include <cuda_fp16.h>
#include <math.h>
#include <stdint.h>

#define N_TOT 8192
#define D     128
#define BM    64     // rows per block
#define BN    128    // cols per streamed tile

__device__ __align__(16) __half g_h[N_TOT * D];   // fp16 normalized features
__device__ float g_loss[N_TOT];

__device__ __forceinline__ float fast_exp2(float x) {
    float y;
    asm("ex2.approx.ftz.f32 %0, %1;" : "=f"(y) : "f"(x));
    return y;
}

// byte offset of 16B chunk (row r, chunk ck in 0..15) in a 256B-pitch tile,
// XOR-swizzled for conflict-free ldmatrix
__device__ __forceinline__ uint32_t sw(int r, int ck) {
    return (uint32_t)(r * 256 + ((ck ^ (r & 7)) << 4));
}

__device__ __forceinline__ void ldmatrix_x4(uint32_t& r0, uint32_t& r1,
                                            uint32_t& r2, uint32_t& r3,
                                            uint32_t addr) {
    asm volatile("ldmatrix.sync.aligned.m8n8.x4.shared.b16 {%0,%1,%2,%3}, [%4];"
                 : "=r"(r0), "=r"(r1), "=r"(r2), "=r"(r3) : "r"(addr) : "memory");
}

__device__ __forceinline__ void mma_f16(float c[4],
                                        uint32_t a0, uint32_t a1, uint32_t a2, uint32_t a3,
                                        uint32_t b0, uint32_t b1) {
    asm volatile("mma.sync.aligned.m16n8k16.row.col.f32.f16.f16.f32 "
                 "{%0,%1,%2,%3},{%4,%5,%6,%7},{%8,%9},{%0,%1,%2,%3};"
                 : "+f"(c[0]), "+f"(c[1]), "+f"(c[2]), "+f"(c[3])
                 : "r"(a0), "r"(a1), "r"(a2), "r"(a3), "r"(b0), "r"(b1));
}

#define CP16(dst, src) \
    asm volatile("cp.async.cg.shared.global [%0], [%1], 16;" :: "r"(dst), "l"(src))

// ---------------------------------------------------------------------------
// Kernel 1: L2-normalize each row, emit fp16 (one warp per row)
// ---------------------------------------------------------------------------
__global__ void normalize_kernel(const float* __restrict__ in) {
    int warp = (blockIdx.x * blockDim.x + threadIdx.x) >> 5;
    int lane = threadIdx.x & 31;
    if (warp >= N_TOT) return;
    float4 v = reinterpret_cast<const float4*>(in + warp * D)[lane];
    float ss = v.x * v.x + v.y * v.y + v.z * v.z + v.w * v.w;
    #pragma unroll
    for (int o = 16; o > 0; o >>= 1)
        ss += __shfl_xor_sync(0xffffffffu, ss, o);
    float scale = 1.0f / fmaxf(sqrtf(ss), 1e-12f);
    __half2 h0 = __floats2half2_rn(v.x * scale, v.y * scale);
    __half2 h1 = __floats2half2_rn(v.z * scale, v.w * scale);
    uint2 pk;
    pk.x = *reinterpret_cast<uint32_t*>(&h0);
    pk.y = *reinterpret_cast<uint32_t*>(&h1);
    reinterpret_cast<uint2*>(g_h + warp * D)[lane] = pk;
}

// ---------------------------------------------------------------------------
// Kernel 2: fp16 tensor-core sim-GEMM + fused logsumexp + positive extraction
// 256 threads (8 warps = 4(m) x 2(n)); block tile 64 x 128; A resident,
// B double-buffered via cp.async; ldmatrix fragment loads.
// ---------------------------------------------------------------------------
__global__ void __launch_bounds__(256) simloss_kernel() {
    extern __shared__ char smem[];
    // layout: As 16KB | Bs0 32KB | Bs1 32KB | part 64f | rsum 128f
    float* part = reinterpret_cast<float*>(smem + 16384 + 65536);
    float* rsum = part + BM;

    const uint32_t smem_b = (uint32_t)__cvta_generic_to_shared(smem);
    const uint32_t As_b   = smem_b;
    const uint32_t Bs_b0  = smem_b + 16384;
    const uint32_t Bs_b1  = smem_b + 16384 + 32768;

    const int t    = threadIdx.x;
    const int lane = t & 31;
    const int w    = t >> 5;
    const int wm   = w >> 1;                // 0..3
    const int wn   = w & 1;                 // 0..1
    const int g    = lane >> 2;             // 0..7
    const int tg   = lane & 3;              // 0..3
    const int rowBase = blockIdx.x * BM;

    // ---- stage A tile (64 rows x 128 k, swizzled) ----
    for (int i = t; i < BM * 16; i += 256) {
        int r = i >> 4, ck = i & 15;
        uint4 v = *reinterpret_cast<const uint4*>(g_h + (rowBase + r) * D + ck * 8);
        *reinterpret_cast<uint4*>(smem + sw(r, ck)) = v;
    }
    if (t < BM) part[t] = 0.0f;

    // ---- issue B tile 0 ----
    const int ld_r  = t >> 4;       // 0..15 (row step 16 per j)
    const int ld_ck = t & 15;
    {
        const __half* src = g_h;    // colBase 0
        #pragma unroll
        for (int j = 0; j < 8; j++) {
            int r = ld_r + j * 16;
            CP16(Bs_b0 + sw(r, ld_ck), src + r * D + ld_ck * 8);
        }
        asm volatile("cp.async.commit_group;");
    }

    // ---- per-lane ldmatrix addresses ----
    const int rowA = wm * 16 + (lane & 15);
    const uint32_t adA_row = As_b + rowA * 256;
    const int rA7 = rowA & 7;
    const int hiA = lane >> 4;                       // 0/1 -> k chunk parity

    const int rbL = (lane & 7) + ((lane >> 4) << 3); // 0..15 within 16-row pair
    const int ckBbit = (lane >> 3) & 1;
    int rowB_[4], rB7_[4];
    #pragma unroll
    for (int p = 0; p < 4; p++) {
        rowB_[p] = wn * 64 + p * 16 + rbL;
        rB7_[p]  = rowB_[p] & 7;
    }

    const float invT = 14.285714285714286f;   // 1/0.07
    const float CEXP = 20.609929869842332f;   // log2(e)/0.07
    const int jtDiag = rowBase >> 7;
    const int jtPos  = (rowBase ^ 4096) >> 7;

    float rs0 = 0.0f, rs1 = 0.0f;

    for (int jt = 0; jt < N_TOT / BN; jt++) {
        // prefetch next tile into the other buffer
        if (jt + 1 < N_TOT / BN) {
            const uint32_t dstb = ((jt + 1) & 1) ? Bs_b1 : Bs_b0;
            const __half* src = g_h + (jt + 1) * BN * D;
            #pragma unroll
            for (int j = 0; j < 8; j++) {
                int r = ld_r + j * 16;
                CP16(dstb + sw(r, ld_ck), src + r * D + ld_ck * 8);
            }
            asm volatile("cp.async.commit_group;");
            asm volatile("cp.async.wait_group 1;");
        } else {
            asm volatile("cp.async.wait_group 0;");
        }
        __syncthreads();

        const uint32_t Bb = (jt & 1) ? Bs_b1 : Bs_b0;

        float c[8][4];
        #pragma unroll
        for (int nt = 0; nt < 8; nt++)
            c[nt][0] = c[nt][1] = c[nt][2] = c[nt][3] = 0.0f;

        #pragma unroll
        for (int kk = 0; kk < 8; kk++) {
            const int ckA = kk * 2 + hiA;
            uint32_t a0, a1, a2, a3;
            ldmatrix_x4(a0, a1, a2, a3, adA_row + ((ckA ^ rA7) << 4));
            const int ckB = kk * 2 + ckBbit;
            #pragma unroll
            for (int p = 0; p < 4; p++) {
                uint32_t b0, b1, b2, b3;
                ldmatrix_x4(b0, b1, b2, b3,
                            Bb + rowB_[p] * 256 + ((ckB ^ rB7_[p]) << 4));
                mma_f16(c[2 * p],     a0, a1, a2, a3, b0, b1);
                mma_f16(c[2 * p + 1], a0, a1, a2, a3, b2, b3);
            }
        }

        if (jt != jtDiag && jt != jtPos) {
            #pragma unroll
            for (int nt = 0; nt < 8; nt++) {
                rs0 += fast_exp2(c[nt][0] * CEXP);
                rs0 += fast_exp2(c[nt][1] * CEXP);
                rs1 += fast_exp2(c[nt][2] * CEXP);
                rs1 += fast_exp2(c[nt][3] * CEXP);
            }
        } else {
            const int gi0 = rowBase + wm * 16 + g;
            const int gi1 = gi0 + 8;
            const int tj0 = gi0 ^ 4096;
            const int tj1 = gi1 ^ 4096;
            #pragma unroll
            for (int nt = 0; nt < 8; nt++) {
                const int col0 = jt * BN + wn * 64 + nt * 8 + tg * 2;
                const int col1 = col0 + 1;
                if (col0 != gi0) rs0 += fast_exp2(c[nt][0] * CEXP);
                if (col1 != gi0) rs0 += fast_exp2(c[nt][1] * CEXP);
                if (col0 != gi1) rs1 += fast_exp2(c[nt][2] * CEXP);
                if (col1 != gi1) rs1 += fast_exp2(c[nt][3] * CEXP);
                if (col0 == tj0) part[wm * 16 + g]     = c[nt][0] * invT;
                if (col1 == tj0) part[wm * 16 + g]     = c[nt][1] * invT;
                if (col0 == tj1) part[wm * 16 + g + 8] = c[nt][2] * invT;
                if (col1 == tj1) part[wm * 16 + g + 8] = c[nt][3] * invT;
            }
        }
        __syncthreads();   // done reading this buffer; safe to overwrite next iter
    }

    // reduce exp-sums over the 4 lanes (tg) sharing each row
    rs0 += __shfl_xor_sync(0xffffffffu, rs0, 1);
    rs0 += __shfl_xor_sync(0xffffffffu, rs0, 2);
    rs1 += __shfl_xor_sync(0xffffffffu, rs1, 1);
    rs1 += __shfl_xor_sync(0xffffffffu, rs1, 2);
    if (tg == 0) {
        rsum[(wm * 16 + g) * 2 + wn]     = rs0;
        rsum[(wm * 16 + g + 8) * 2 + wn] = rs1;
    }
    __syncthreads();

    if (t < BM) {
        float total = rsum[t * 2] + rsum[t * 2 + 1];
        g_loss[rowBase + t] = logf(total) - part[t];
    }
}

// ---------------------------------------------------------------------------
// Kernel 3: mean over rows -> output
// ---------------------------------------------------------------------------
__global__ void reduce_kernel(float* __restrict__ out, int out_size) {
    __shared__ float ssum[256];
    float s = 0.0f;
    for (int i = threadIdx.x; i < N_TOT; i += 256) s += g_loss[i];
    ssum[threadIdx.x] = s;
    __syncthreads();
    #pragma unroll
    for (int o = 128; o > 0; o >>= 1) {
        if (threadIdx.x < o) ssum[threadIdx.x] += ssum[threadIdx.x + o];
        __syncthreads();
    }
    const float mean = ssum[0] * (1.0f / (float)N_TOT);
    for (int i = threadIdx.x; i < out_size; i += 256) out[i] = mean;
}

extern "C" void kernel_launch(void* const* d_in, const int* in_sizes, int n_in,
                              void* d_out, int out_size) {
    (void)in_sizes; (void)n_in;
    const float* features = (const float*)d_in[0];
    float* out = (float*)d_out;

    const int smem_bytes = 16384 + 65536 + (BM + 2 * BM) * (int)sizeof(float);
    cudaFuncSetAttribute(simloss_kernel,
                         cudaFuncAttributeMaxDynamicSharedMemorySize, smem_bytes);

    normalize_kernel<<<N_TOT / 8, 256>>>(features);
    simloss_kernel<<<N_TOT / BM, 256, smem_bytes>>>();
    reduce_kernel<<<1, 256>>>(out, out_size);
}

// round 5
// speedup vs baseline: 24.2412x; 1.6252x over previous
#include <cuda_runtime.h>
#include <cuda_fp16.h>
#include <math.h>
#include <stdint.h>

#define N_TOT 8192
#define D     128
#define G     64        // 64 row-groups of 128 rows
#define NTRI  2080      // 64 diag + 2016 upper off-diag tiles
#define NBLK  148

__device__ __align__(16) __half g_h[N_TOT * D];   // fp16 normalized features
__device__ float g_acc[G * G * 128];              // per-(target,other) group partials
__device__ float g_pos[N_TOT];
__device__ float g_loss[N_TOT];

// dynamic smem offsets
#define OFF_A0 0
#define OFF_A1 32768
#define OFF_B0 65536
#define OFF_B1 98304
#define OFF_RP 131072                    // 128*2 floats
#define OFF_CP (OFF_RP + 1024)           // 128*4 floats
#define SMEM_DYN (OFF_CP + 2048)

__device__ __forceinline__ float fast_exp2(float x) {
    float y;
    asm("ex2.approx.ftz.f32 %0, %1;" : "=f"(y) : "f"(x));
    return y;
}

// XOR-swizzled 256B-pitch tile offset (row r 0..127, 16B chunk ck 0..15)
__device__ __forceinline__ uint32_t sw(int r, int ck) {
    return (uint32_t)(r * 256 + ((ck ^ (r & 7)) << 4));
}

__device__ __forceinline__ void ldmatrix_x4(uint32_t& r0, uint32_t& r1,
                                            uint32_t& r2, uint32_t& r3,
                                            uint32_t addr) {
    asm volatile("ldmatrix.sync.aligned.m8n8.x4.shared.b16 {%0,%1,%2,%3}, [%4];"
                 : "=r"(r0), "=r"(r1), "=r"(r2), "=r"(r3) : "r"(addr) : "memory");
}

__device__ __forceinline__ void mma_f16(float c[4],
                                        uint32_t a0, uint32_t a1, uint32_t a2, uint32_t a3,
                                        uint32_t b0, uint32_t b1) {
    asm volatile("mma.sync.aligned.m16n8k16.row.col.f32.f16.f16.f32 "
                 "{%0,%1,%2,%3},{%4,%5,%6,%7},{%8,%9},{%0,%1,%2,%3};"
                 : "+f"(c[0]), "+f"(c[1]), "+f"(c[2]), "+f"(c[3])
                 : "r"(a0), "r"(a1), "r"(a2), "r"(a3), "r"(b0), "r"(b1));
}

#define CP16(dst, src) \
    asm volatile("cp.async.cg.shared.global [%0], [%1], 16;" :: "r"(dst), "l"(src))

__device__ __forceinline__ void decode_tile(int t, int& I, int& J) {
    int i = 0;
    while (t >= G - i) { t -= G - i; i++; }
    I = i; J = i + t;
}

// ---------------------------------------------------------------------------
// Kernel 1: L2-normalize each row, emit fp16 (one warp per row)
// ---------------------------------------------------------------------------
__global__ void normalize_kernel(const float* __restrict__ in) {
    int warp = (blockIdx.x * blockDim.x + threadIdx.x) >> 5;
    int lane = threadIdx.x & 31;
    if (warp >= N_TOT) return;
    float4 v = reinterpret_cast<const float4*>(in + warp * D)[lane];
    float ss = v.x * v.x + v.y * v.y + v.z * v.z + v.w * v.w;
    #pragma unroll
    for (int o = 16; o > 0; o >>= 1)
        ss += __shfl_xor_sync(0xffffffffu, ss, o);
    float scale = 1.0f / fmaxf(sqrtf(ss), 1e-12f);
    __half2 h0 = __floats2half2_rn(v.x * scale, v.y * scale);
    __half2 h1 = __floats2half2_rn(v.z * scale, v.w * scale);
    uint2 pk;
    pk.x = *reinterpret_cast<uint32_t*>(&h0);
    pk.y = *reinterpret_cast<uint32_t*>(&h1);
    reinterpret_cast<uint2*>(g_h + warp * D)[lane] = pk;
}

// ---------------------------------------------------------------------------
// Kernel 2: symmetric persistent fp16 mma.sync sim-GEMM, upper-tri tiles only.
// 148 blocks x 256 threads (8 warps: wm = w&3 -> 32 rows, wn = w>>2 -> 64 cols).
// Per tile (I,J): row-sums of exp -> g_acc[I*G+J], col-sums -> g_acc[J*G+I].
// ---------------------------------------------------------------------------
__global__ void __launch_bounds__(256) simloss_kernel() {
    extern __shared__ char smem[];
    const uint32_t sb = (uint32_t)__cvta_generic_to_shared(smem);
    float* rp2 = reinterpret_cast<float*>(smem + OFF_RP);   // [128][2] by wn
    float* cp2 = reinterpret_cast<float*>(smem + OFF_CP);   // [128][4] by wm

    const int t    = threadIdx.x;
    const int lane = t & 31;
    const int w    = t >> 5;
    const int wm   = w & 3;
    const int wn   = w >> 2;
    const int g    = lane >> 2;
    const int tg   = lane & 3;

    const int ld_r = t >> 4, ld_ck = t & 15;
    auto stage = [&](uint32_t Adst, uint32_t Bdst, int I, int J) {
        const __half* srcA = g_h + (size_t)(I * 128) * D;
        const __half* srcB = g_h + (size_t)(J * 128) * D;
        #pragma unroll
        for (int j = 0; j < 8; j++) {
            int r = ld_r + j * 16;
            CP16(Adst + sw(r, ld_ck), srcA + r * D + ld_ck * 8);
        }
        #pragma unroll
        for (int j = 0; j < 8; j++) {
            int r = ld_r + j * 16;
            CP16(Bdst + sw(r, ld_ck), srcB + r * D + ld_ck * 8);
        }
        asm volatile("cp.async.commit_group;" ::: "memory");
    };

    // per-lane fragment address helpers
    const int laneLo = lane & 15;
    const int hiA    = lane >> 4;
    const int rbL    = (lane & 7) + ((lane >> 4) << 3);
    const int ckBbit = (lane >> 3) & 1;

    const float invT = 14.285714285714286f;
    const float CEXP = 20.609929869842332f;   // log2(e)/0.07

    int tcur = blockIdx.x;
    if (tcur >= NTRI) return;
    int I, J;
    decode_tile(tcur, I, J);
    stage(sb + OFF_A0, sb + OFF_B0, I, J);

    int buf = 0;
    while (tcur < NTRI) {
        const int tnext = tcur + NBLK;
        int nI = 0, nJ = 0;
        const bool hasNext = (tnext < NTRI);
        if (hasNext) {
            decode_tile(tnext, nI, nJ);
            stage(sb + (buf ? OFF_A0 : OFF_A1), sb + (buf ? OFF_B0 : OFF_B1), nI, nJ);
            asm volatile("cp.async.wait_group 1;" ::: "memory");
        } else {
            asm volatile("cp.async.wait_group 0;" ::: "memory");
        }
        __syncthreads();   // tiles staged; also separates prev write-out from rp2/cp2 reuse

        const uint32_t Ab = sb + (buf ? OFF_A1 : OFF_A0);
        const uint32_t Bb = sb + (buf ? OFF_B1 : OFF_B0);

        float c[2][8][4];
        #pragma unroll
        for (int mt = 0; mt < 2; mt++)
            #pragma unroll
            for (int nt = 0; nt < 8; nt++)
                c[mt][nt][0] = c[mt][nt][1] = c[mt][nt][2] = c[mt][nt][3] = 0.0f;

        #pragma unroll
        for (int kk = 0; kk < 8; kk++) {
            uint32_t aF[2][4];
            #pragma unroll
            for (int mt = 0; mt < 2; mt++) {
                const int rowA = wm * 32 + mt * 16 + laneLo;
                const int ckA  = kk * 2 + hiA;
                ldmatrix_x4(aF[mt][0], aF[mt][1], aF[mt][2], aF[mt][3],
                            Ab + rowA * 256 + (((ckA) ^ (rowA & 7)) << 4));
            }
            const int ckB = kk * 2 + ckBbit;
            #pragma unroll
            for (int p = 0; p < 4; p++) {
                const int rowB = wn * 64 + p * 16 + rbL;
                uint32_t b0, b1, b2, b3;
                ldmatrix_x4(b0, b1, b2, b3,
                            Bb + rowB * 256 + ((ckB ^ (rowB & 7)) << 4));
                #pragma unroll
                for (int mt = 0; mt < 2; mt++) {
                    mma_f16(c[mt][2 * p],     aF[mt][0], aF[mt][1], aF[mt][2], aF[mt][3], b0, b1);
                    mma_f16(c[mt][2 * p + 1], aF[mt][0], aF[mt][1], aF[mt][2], aF[mt][3], b2, b3);
                }
            }
        }

        // ---- epilogue ----
        const bool isDiag = (I == J);
        const bool isPos  = (J == I + 32);

        float rs[2][2] = {{0.f, 0.f}, {0.f, 0.f}};   // [mt][g-half]
        float cs0[8], cs1[8];
        #pragma unroll
        for (int nt = 0; nt < 8; nt++) { cs0[nt] = 0.f; cs1[nt] = 0.f; }

        #pragma unroll
        for (int mt = 0; mt < 2; mt++) {
            const int lr0 = wm * 32 + mt * 16 + g;
            const int lr1 = lr0 + 8;
            #pragma unroll
            for (int nt = 0; nt < 8; nt++) {
                const int lc0 = wn * 64 + nt * 8 + tg * 2;
                const int lc1 = lc0 + 1;
                float v0 = c[mt][nt][0], v1 = c[mt][nt][1];
                float v2 = c[mt][nt][2], v3 = c[mt][nt][3];
                float e0 = fast_exp2(v0 * CEXP), e1 = fast_exp2(v1 * CEXP);
                float e2 = fast_exp2(v2 * CEXP), e3 = fast_exp2(v3 * CEXP);
                if (isDiag) {
                    if (lr0 == lc0) e0 = 0.f;
                    if (lr0 == lc1) e1 = 0.f;
                    if (lr1 == lc0) e2 = 0.f;
                    if (lr1 == lc1) e3 = 0.f;
                } else if (isPos) {
                    if (lr0 == lc0) { float pv = v0 * invT; int i0 = I * 128 + lr0; g_pos[i0] = pv; g_pos[i0 + 4096] = pv; }
                    if (lr0 == lc1) { float pv = v1 * invT; int i0 = I * 128 + lr0; g_pos[i0] = pv; g_pos[i0 + 4096] = pv; }
                    if (lr1 == lc0) { float pv = v2 * invT; int i0 = I * 128 + lr1; g_pos[i0] = pv; g_pos[i0 + 4096] = pv; }
                    if (lr1 == lc1) { float pv = v3 * invT; int i0 = I * 128 + lr1; g_pos[i0] = pv; g_pos[i0 + 4096] = pv; }
                }
                rs[mt][0] += e0 + e1;
                rs[mt][1] += e2 + e3;
                cs0[nt] += e0 + e2;
                cs1[nt] += e1 + e3;
            }
        }

        // reduce row-sums over tg (4 lanes per row)
        #pragma unroll
        for (int mt = 0; mt < 2; mt++) {
            #pragma unroll
            for (int h = 0; h < 2; h++) {
                float v = rs[mt][h];
                v += __shfl_xor_sync(0xffffffffu, v, 1);
                v += __shfl_xor_sync(0xffffffffu, v, 2);
                rs[mt][h] = v;
            }
        }
        if (tg == 0) {
            #pragma unroll
            for (int mt = 0; mt < 2; mt++) {
                rp2[(wm * 32 + mt * 16 + g) * 2 + wn]     = rs[mt][0];
                rp2[(wm * 32 + mt * 16 + g + 8) * 2 + wn] = rs[mt][1];
            }
        }

        // reduce col-sums over g (8 lanes per col pair)
        #pragma unroll
        for (int nt = 0; nt < 8; nt++) {
            float v0 = cs0[nt], v1 = cs1[nt];
            #pragma unroll
            for (int o = 4; o <= 16; o <<= 1) {
                v0 += __shfl_xor_sync(0xffffffffu, v0, o);
                v1 += __shfl_xor_sync(0xffffffffu, v1, o);
            }
            cs0[nt] = v0; cs1[nt] = v1;
        }
        if (lane < 4) {
            #pragma unroll
            for (int nt = 0; nt < 8; nt++) {
                const int col = wn * 64 + nt * 8 + lane * 2;
                cp2[col * 4 + wm]       = cs0[nt];
                cp2[(col + 1) * 4 + wm] = cs1[nt];
            }
        }
        __syncthreads();

        if (t < 128) {
            float rv = rp2[t * 2] + rp2[t * 2 + 1];
            g_acc[(I * G + J) * 128 + t] = rv;
            if (!isDiag) {
                float cv = cp2[t * 4] + cp2[t * 4 + 1] + cp2[t * 4 + 2] + cp2[t * 4 + 3];
                g_acc[(J * G + I) * 128 + t] = cv;
            }
        }

        buf ^= 1;
        tcur = tnext;
        I = nI; J = nJ;
    }
}

// ---------------------------------------------------------------------------
// Kernel 3: per-row loss
// ---------------------------------------------------------------------------
__global__ void loss_kernel() {
    const int i = blockIdx.x * 256 + threadIdx.x;
    const int I = i >> 7, r = i & 127;
    float s = 0.0f;
    #pragma unroll 8
    for (int O = 0; O < G; O++) s += g_acc[(I * G + O) * 128 + r];
    g_loss[i] = logf(s) - g_pos[i];
}

// ---------------------------------------------------------------------------
// Kernel 4: mean over rows -> output
// ---------------------------------------------------------------------------
__global__ void reduce_kernel(float* __restrict__ out, int out_size) {
    __shared__ float ssum[256];
    float s = 0.0f;
    for (int i = threadIdx.x; i < N_TOT; i += 256) s += g_loss[i];
    ssum[threadIdx.x] = s;
    __syncthreads();
    #pragma unroll
    for (int o = 128; o > 0; o >>= 1) {
        if (threadIdx.x < o) ssum[threadIdx.x] += ssum[threadIdx.x + o];
        __syncthreads();
    }
    const float mean = ssum[0] * (1.0f / (float)N_TOT);
    for (int i = threadIdx.x; i < out_size; i += 256) out[i] = mean;
}

extern "C" void kernel_launch(void* const* d_in, const int* in_sizes, int n_in,
                              void* d_out, int out_size) {
    (void)in_sizes; (void)n_in;
    const float* features = (const float*)d_in[0];
    float* out = (float*)d_out;

    cudaFuncSetAttribute(simloss_kernel,
                         cudaFuncAttributeMaxDynamicSharedMemorySize, SMEM_DYN);

    normalize_kernel<<<N_TOT / 8, 256>>>(features);
    simloss_kernel<<<NBLK, 256, SMEM_DYN>>>();
    loss_kernel<<<N_TOT / 256, 256>>>();
    reduce_kernel<<<1, 256>>>(out, out_size);
}